// round 2
// baseline (speedup 1.0000x reference)
#include <cuda_runtime.h>
#include <cstdint>
#include <cstddef>

#define N_REC   256
#define T_STEPS 1000
#define NI      3
#define NO      3
#define ALPHA_F 0.2f
#define LEAK_F  0.8f
#define NOISE_SCALE_F 0.03162277660168379f

#define WPAD 132
// floats: rbuf 2*2*256 = 1024 ; wsh 256*132 = 33792 ; opart 2*8*6 = 96
#define SMEM_FLOATS (1024 + N_REC * WPAD + 96)
#define SMEM_BYTES  (SMEM_FLOATS * 4)

__device__ __forceinline__ unsigned long long pk2(float x, float y) {
    unsigned long long r;
    asm("mov.b64 %0, {%1, %2};" : "=l"(r) : "f"(x), "f"(y));
    return r;
}
__device__ __forceinline__ void upk2(unsigned long long v, float& x, float& y) {
    asm("mov.b64 {%0, %1}, %2;" : "=f"(x), "=f"(y) : "l"(v));
}
// Blackwell packed dual-fp32 FMA (sm_100+): 2 MACs per instruction.
__device__ __forceinline__ unsigned long long ffma2(unsigned long long a,
                                                    unsigned long long b,
                                                    unsigned long long c) {
    unsigned long long d;
    asm("fma.rn.f32x2 %0, %1, %2, %3;" : "=l"(d) : "l"(a), "l"(b), "l"(c));
    return d;
}

__global__ __launch_bounds__(256, 1)
void rnn_persistent_kernel(const float* __restrict__ x,
                           const float* __restrict__ noise,
                           const float* __restrict__ W_in,
                           const float* __restrict__ W_rec,
                           const float* __restrict__ W_out_w,
                           const float* __restrict__ W_out_b,
                           const float* __restrict__ bias,
                           float* __restrict__ out)
{
    extern __shared__ float smem[];
    float* rbuf  = smem;                   // [2 buf][2 batch][256]
    float* wsh   = smem + 1024;            // [256][WPAD], holds W_rec[:,128:256]
    float* opart = wsh + N_REC * WPAD;     // [2 parity][8 warp][6]

    const int tid  = threadIdx.x;          // = neuron index n
    const int lane = tid & 31;
    const int warp = tid >> 5;
    const int b0   = blockIdx.x * 2;       // two batches per CTA

    // ---- W_rec row n, k in [0,128): 128 registers as 64 packed f32x2 pairs ----
    unsigned long long w[64];
    {
        const float4* wr4 = reinterpret_cast<const float4*>(W_rec + (size_t)tid * N_REC);
        #pragma unroll
        for (int i = 0; i < 32; i++) {
            float4 v = wr4[i];
            w[2 * i]     = pk2(v.x, v.y);
            w[2 * i + 1] = pk2(v.z, v.w);
        }
    }
    // ---- W_rec[:, 128:256) -> SMEM, padded rows (conflict-free LDS.128) ----
    for (int idx = tid; idx < N_REC * 128; idx += 256) {
        int row = idx >> 7, col = idx & 127;
        wsh[row * WPAD + col] = W_rec[row * N_REC + 128 + col];
    }

    const float wi0 = W_in[tid * 3 + 0], wi1 = W_in[tid * 3 + 1], wi2 = W_in[tid * 3 + 2];
    const float bi  = bias[tid];
    const float wo0 = W_out_w[0 * N_REC + tid];
    const float wo1 = W_out_w[1 * N_REC + tid];
    const float wo2 = W_out_w[2 * N_REC + tid];
    const float ob  = (tid < 6) ? W_out_b[tid % 3] : 0.f;

    // initial state r = 0 in buffer 0
    rbuf[tid] = 0.f;
    rbuf[256 + tid] = 0.f;

    const float* nzp0 = noise + (size_t)b0 * T_STEPS * N_REC + tid;
    const float* nzp1 = nzp0 + (size_t)T_STEPS * N_REC;
    const float* xp0  = x + (size_t)b0 * T_STEPS * NI;
    const float* xp1  = xp0 + (size_t)T_STEPS * NI;

    float rold0 = 0.f, rold1 = 0.f;

    __syncthreads();

    const float4* wsv = reinterpret_cast<const float4*>(wsh + tid * WPAD);

    for (int t = 0; t < T_STEPS; t++) {
        const int cur = t & 1, nxt = cur ^ 1;

        // prefetch drive inputs for THIS step (used only after the long dot phase)
        const float nz0 = __ldg(nzp0 + t * N_REC);
        const float nz1 = __ldg(nzp1 + t * N_REC);
        const float x00 = __ldg(xp0 + t * 3 + 0);
        const float x01 = __ldg(xp0 + t * 3 + 1);
        const float x02 = __ldg(xp0 + t * 3 + 2);
        const float x10 = __ldg(xp1 + t * 3 + 0);
        const float x11 = __ldg(xp1 + t * 3 + 1);
        const float x12 = __ldg(xp1 + t * 3 + 2);

        // emit previous step's output (off critical path, 6 threads)
        if (t > 0 && tid < 6) {
            const int par = (t - 1) & 1;
            float s = ob;
            #pragma unroll
            for (int w8 = 0; w8 < 8; w8++) s += opart[par * 48 + w8 * 6 + tid];
            const int bb = tid / 3, oo = tid - bb * 3;
            out[((size_t)(b0 + bb) * T_STEPS + (t - 1)) * NO + oo] = s;
        }

        const float4* r0v = reinterpret_cast<const float4*>(rbuf + cur * 512);
        const float4* r1v = r0v + 64;   // + 256 floats = batch 1

        unsigned long long A0 = 0, B0 = 0, A1 = 0, B1 = 0;
        // k in [0,128): W from registers
        #pragma unroll
        for (int i = 0; i < 32; i++) {
            float4 q0 = r0v[i];
            A0 = ffma2(w[2 * i],     pk2(q0.x, q0.y), A0);
            B0 = ffma2(w[2 * i + 1], pk2(q0.z, q0.w), B0);
            float4 q1 = r1v[i];
            A1 = ffma2(w[2 * i],     pk2(q1.x, q1.y), A1);
            B1 = ffma2(w[2 * i + 1], pk2(q1.z, q1.w), B1);
        }
        // k in [128,256): W from SMEM (reused across both batches)
        #pragma unroll
        for (int i = 0; i < 32; i++) {
            float4 wv = wsv[i];
            unsigned long long w0 = pk2(wv.x, wv.y);
            unsigned long long w1 = pk2(wv.z, wv.w);
            float4 q0 = r0v[32 + i];
            A0 = ffma2(w0, pk2(q0.x, q0.y), A0);
            B0 = ffma2(w1, pk2(q0.z, q0.w), B0);
            float4 q1 = r1v[32 + i];
            A1 = ffma2(w0, pk2(q1.x, q1.y), A1);
            B1 = ffma2(w1, pk2(q1.z, q1.w), B1);
        }
        float a0x, a0y, c0x, c0y, a1x, a1y, c1x, c1y;
        upk2(A0, a0x, a0y); upk2(B0, c0x, c0y);
        upk2(A1, a1x, a1y); upk2(B1, c1x, c1y);
        const float dot0 = (a0x + a0y) + (c0x + c0y);
        const float dot1 = (a1x + a1y) + (c1x + c1y);

        const float u0 = fmaf(NOISE_SCALE_F, nz0, bi) + x00 * wi0 + x01 * wi1 + x02 * wi2;
        const float u1 = fmaf(NOISE_SCALE_F, nz1, bi) + x10 * wi0 + x11 * wi1 + x12 * wi2;

        const float rn0 = LEAK_F * rold0 + ALPHA_F * fmaxf(dot0 + u0, 0.f);
        const float rn1 = LEAK_F * rold1 + ALPHA_F * fmaxf(dot1 + u1, 0.f);
        rold0 = rn0; rold1 = rn1;
        rbuf[nxt * 512 + tid]       = rn0;
        rbuf[nxt * 512 + 256 + tid] = rn1;

        // output projection partials: warp-level reduce of 6 values
        float p0 = rn0 * wo0, p1 = rn0 * wo1, p2 = rn0 * wo2;
        float p3 = rn1 * wo0, p4 = rn1 * wo1, p5 = rn1 * wo2;
        #pragma unroll
        for (int off = 16; off > 0; off >>= 1) {
            p0 += __shfl_xor_sync(0xffffffffu, p0, off);
            p1 += __shfl_xor_sync(0xffffffffu, p1, off);
            p2 += __shfl_xor_sync(0xffffffffu, p2, off);
            p3 += __shfl_xor_sync(0xffffffffu, p3, off);
            p4 += __shfl_xor_sync(0xffffffffu, p4, off);
            p5 += __shfl_xor_sync(0xffffffffu, p5, off);
        }
        if (lane == 0) {
            float* dst = opart + cur * 48 + warp * 6;
            dst[0] = p0; dst[1] = p1; dst[2] = p2;
            dst[3] = p3; dst[4] = p4; dst[5] = p5;
        }
        __syncthreads();
    }

    // final step's output (t = T-1)
    if (tid < 6) {
        const int par = (T_STEPS - 1) & 1;
        float s = ob;
        #pragma unroll
        for (int w8 = 0; w8 < 8; w8++) s += opart[par * 48 + w8 * 6 + tid];
        const int bb = tid / 3, oo = tid - bb * 3;
        out[((size_t)(b0 + bb) * T_STEPS + (T_STEPS - 1)) * NO + oo] = s;
    }
}

extern "C" void kernel_launch(void* const* d_in, const int* in_sizes, int n_in,
                              void* d_out, int out_size)
{
    const float* x       = (const float*)d_in[0];
    const float* noise   = (const float*)d_in[1];
    const float* W_in    = (const float*)d_in[2];
    const float* W_rec   = (const float*)d_in[3];
    const float* W_out_w = (const float*)d_in[4];
    const float* W_out_b = (const float*)d_in[5];
    const float* bias    = (const float*)d_in[6];
    float* out = (float*)d_out;

    // One-time host-side config: runs before the first (uncaptured) correctness
    // call; never executed during graph capture. Idempotent, no work-state.
    static bool attr_done = false;
    if (!attr_done) {
        (void)cudaFuncSetAttribute(rnn_persistent_kernel,
                                   cudaFuncAttributeMaxDynamicSharedMemorySize,
                                   SMEM_BYTES);
        attr_done = true;
    }

    rnn_persistent_kernel<<<128, 256, SMEM_BYTES>>>(
        x, noise, W_in, W_rec, W_out_w, W_out_b, bias, out);
}

// round 5
// speedup vs baseline: 1.0554x; 1.0554x over previous
#include <cuda_runtime.h>
#include <cstdint>
#include <cstddef>

#define N_REC   256
#define T_STEPS 1000
#define NI      3
#define NO      3
#define ALPHA_F 0.2f
#define LEAK_F  0.8f
#define NOISE_SCALE_F 0.03162277660168379f

#define WPAD 132
// floats: rbuf 2*2*256 = 1024 ; wsh 256*132 = 33792 ; wout 3*256 = 768 ; bias 4
#define SMEM_FLOATS (1024 + N_REC * WPAD + 768 + 4)
#define SMEM_BYTES  (SMEM_FLOATS * 4)

__device__ __forceinline__ unsigned long long pk2(float x, float y) {
    unsigned long long r;
    asm("mov.b64 %0, {%1, %2};" : "=l"(r) : "f"(x), "f"(y));
    return r;
}
__device__ __forceinline__ void upk2(unsigned long long v, float& x, float& y) {
    asm("mov.b64 {%0, %1}, %2;" : "=f"(x), "=f"(y) : "l"(v));
}
// Blackwell packed dual-fp32 FMA (sm_100+): 2 MACs per instruction.
__device__ __forceinline__ unsigned long long ffma2(unsigned long long a,
                                                    unsigned long long b,
                                                    unsigned long long c) {
    unsigned long long d;
    asm("fma.rn.f32x2 %0, %1, %2, %3;" : "=l"(d) : "l"(a), "l"(b), "l"(c));
    return d;
}

// Output projection for one batch's step, executed by ONE warp (warps 6/7),
// overlapped with the other warps' dot phase. rb = rbuf slice (256 floats).
__device__ __forceinline__ void emit_out(const float* __restrict__ rb,
                                         const float* __restrict__ wout_s,
                                         const float* __restrict__ wb3,
                                         float* __restrict__ out,
                                         int bidx, int tstore, int lane)
{
    const float4* rv = reinterpret_cast<const float4*>(rb);
    float4 ra = rv[lane];        // r[4l .. 4l+4)
    float4 rc = rv[32 + lane];   // r[128+4l .. 128+4l+4)
    const float4* w0 = reinterpret_cast<const float4*>(wout_s);
    const float4* w1 = reinterpret_cast<const float4*>(wout_s + 256);
    const float4* w2 = reinterpret_cast<const float4*>(wout_s + 512);
    float4 a0 = w0[lane], c0 = w0[32 + lane];
    float4 a1 = w1[lane], c1 = w1[32 + lane];
    float4 a2 = w2[lane], c2 = w2[32 + lane];

    float p0 = ra.x*a0.x + ra.y*a0.y + ra.z*a0.z + ra.w*a0.w
             + rc.x*c0.x + rc.y*c0.y + rc.z*c0.z + rc.w*c0.w;
    float p1 = ra.x*a1.x + ra.y*a1.y + ra.z*a1.z + ra.w*a1.w
             + rc.x*c1.x + rc.y*c1.y + rc.z*c1.z + rc.w*c1.w;
    float p2 = ra.x*a2.x + ra.y*a2.y + ra.z*a2.z + ra.w*a2.w
             + rc.x*c2.x + rc.y*c2.y + rc.z*c2.z + rc.w*c2.w;

    #pragma unroll
    for (int off = 16; off > 0; off >>= 1) {
        p0 += __shfl_xor_sync(0xffffffffu, p0, off);
        p1 += __shfl_xor_sync(0xffffffffu, p1, off);
        p2 += __shfl_xor_sync(0xffffffffu, p2, off);
    }
    if (lane == 0) {
        float* o = out + ((size_t)bidx * T_STEPS + tstore) * NO;
        o[0] = p0 + wb3[0];
        o[1] = p1 + wb3[1];
        o[2] = p2 + wb3[2];
    }
}

__global__ __launch_bounds__(256, 1)
void rnn_persistent_kernel(const float* __restrict__ x,
                           const float* __restrict__ noise,
                           const float* __restrict__ W_in,
                           const float* __restrict__ W_rec,
                           const float* __restrict__ W_out_w,
                           const float* __restrict__ W_out_b,
                           const float* __restrict__ bias,
                           float* __restrict__ out)
{
    extern __shared__ float smem[];
    float* rbuf   = smem;                     // [2 buf][2 batch][256]
    float* wsh    = smem + 1024;              // [256][WPAD] : W_rec[:,128:256)
    float* wout_s = wsh + N_REC * WPAD;       // [3][256]
    float* wb3    = wout_s + 768;             // [3] + pad

    const int tid  = threadIdx.x;             // neuron index n
    const int lane = tid & 31;
    const int warp = tid >> 5;
    const int b0   = blockIdx.x * 2;          // two batches per CTA

    // ---- W_rec row n, k in [0,128): 128 registers as 64 packed f32x2 pairs ----
    unsigned long long w[64];
    {
        const float4* wr4 = reinterpret_cast<const float4*>(W_rec + (size_t)tid * N_REC);
        #pragma unroll
        for (int i = 0; i < 32; i++) {
            float4 v = wr4[i];
            w[2 * i]     = pk2(v.x, v.y);
            w[2 * i + 1] = pk2(v.z, v.w);
        }
    }
    // ---- W_rec[:, 128:256) -> SMEM, padded rows ----
    for (int idx = tid; idx < N_REC * 128; idx += 256) {
        int row = idx >> 7, col = idx & 127;
        wsh[row * WPAD + col] = W_rec[row * N_REC + 128 + col];
    }
    // ---- W_out / bias -> SMEM ----
    for (int idx = tid; idx < NO * N_REC; idx += 256) wout_s[idx] = W_out_w[idx];
    if (tid < NO) wb3[tid] = W_out_b[tid];

    const float wi0 = W_in[tid * 3 + 0], wi1 = W_in[tid * 3 + 1], wi2 = W_in[tid * 3 + 2];
    const float bi  = bias[tid];

    // initial state r = 0 in buffer 0
    rbuf[tid] = 0.f;
    rbuf[256 + tid] = 0.f;

    const float* nzp0 = noise + (size_t)b0 * T_STEPS * N_REC + tid;
    const float* nzp1 = nzp0 + (size_t)T_STEPS * N_REC;
    const float* xp0  = x + (size_t)b0 * T_STEPS * NI;
    const float* xp1  = xp0 + (size_t)T_STEPS * NI;

    float rold0 = 0.f, rold1 = 0.f;

    __syncthreads();

    const float4* wsv = reinterpret_cast<const float4*>(wsh + tid * WPAD);

    for (int t = 0; t < T_STEPS; t++) {
        const int cur = t & 1, nxt = cur ^ 1;

        // prefetch drive inputs for THIS step
        const float nz0 = __ldg(nzp0 + t * N_REC);
        const float nz1 = __ldg(nzp1 + t * N_REC);
        const float x00 = __ldg(xp0 + t * 3 + 0);
        const float x01 = __ldg(xp0 + t * 3 + 1);
        const float x02 = __ldg(xp0 + t * 3 + 2);
        const float x10 = __ldg(xp1 + t * 3 + 0);
        const float x11 = __ldg(xp1 + t * 3 + 1);
        const float x12 = __ldg(xp1 + t * 3 + 2);

        // warps 6/7: emit previous step's output (overlaps with others' dot)
        if (t > 0 && warp >= 6) {
            const float* rb = rbuf + cur * 512 + (warp - 6) * 256;
            emit_out(rb, wout_s, wb3, out, b0 + (warp - 6), t - 1, lane);
        }

        const float4* r0v = reinterpret_cast<const float4*>(rbuf + cur * 512);
        const float4* r1v = r0v + 64;   // + 256 floats = batch 1

        // 8 accumulator chains (parity-split), reg-W and smem-W fused per iter
        unsigned long long s0[2] = {0, 0}, t0a[2] = {0, 0};
        unsigned long long s1[2] = {0, 0}, t1a[2] = {0, 0};
        #pragma unroll
        for (int i = 0; i < 32; i++) {
            const int p = i & 1;
            float4 wv  = wsv[i];              // W[:,128+4i..+4) (conflict-free)
            float4 q0l = r0v[i];              // r b0, k-low (broadcast)
            float4 q1l = r1v[i];              // r b1, k-low
            float4 q0h = r0v[32 + i];         // r b0, k-high
            float4 q1h = r1v[32 + i];         // r b1, k-high
            unsigned long long wp0 = pk2(wv.x, wv.y);
            unsigned long long wp1 = pk2(wv.z, wv.w);
            s0[p]  = ffma2(w[2 * i],     pk2(q0l.x, q0l.y), s0[p]);
            t0a[p] = ffma2(w[2 * i + 1], pk2(q0l.z, q0l.w), t0a[p]);
            s1[p]  = ffma2(w[2 * i],     pk2(q1l.x, q1l.y), s1[p]);
            t1a[p] = ffma2(w[2 * i + 1], pk2(q1l.z, q1l.w), t1a[p]);
            s0[p]  = ffma2(wp0, pk2(q0h.x, q0h.y), s0[p]);
            t0a[p] = ffma2(wp1, pk2(q0h.z, q0h.w), t0a[p]);
            s1[p]  = ffma2(wp0, pk2(q1h.x, q1h.y), s1[p]);
            t1a[p] = ffma2(wp1, pk2(q1h.z, q1h.w), t1a[p]);
        }
        float e0, e1, e2, e3, e4, e5, e6, e7;
        upk2(s0[0], e0, e1); upk2(s0[1], e2, e3);
        upk2(t0a[0], e4, e5); upk2(t0a[1], e6, e7);
        const float dot0 = ((e0 + e1) + (e2 + e3)) + ((e4 + e5) + (e6 + e7));
        upk2(s1[0], e0, e1); upk2(s1[1], e2, e3);
        upk2(t1a[0], e4, e5); upk2(t1a[1], e6, e7);
        const float dot1 = ((e0 + e1) + (e2 + e3)) + ((e4 + e5) + (e6 + e7));

        const float u0 = fmaf(NOISE_SCALE_F, nz0, bi) + x00 * wi0 + x01 * wi1 + x02 * wi2;
        const float u1 = fmaf(NOISE_SCALE_F, nz1, bi) + x10 * wi0 + x11 * wi1 + x12 * wi2;

        const float rn0 = LEAK_F * rold0 + ALPHA_F * fmaxf(dot0 + u0, 0.f);
        const float rn1 = LEAK_F * rold1 + ALPHA_F * fmaxf(dot1 + u1, 0.f);
        rold0 = rn0; rold1 = rn1;
        rbuf[nxt * 512 + tid]       = rn0;
        rbuf[nxt * 512 + 256 + tid] = rn1;

        __syncthreads();
    }

    // final step's output (t = T-1): final r lives in buffer (T_STEPS & 1) = 0
    if (warp >= 6) {
        const float* rb = rbuf + ((T_STEPS & 1) * 512) + (warp - 6) * 256;
        emit_out(rb, wout_s, wb3, out, b0 + (warp - 6), T_STEPS - 1, lane);
    }
}

extern "C" void kernel_launch(void* const* d_in, const int* in_sizes, int n_in,
                              void* d_out, int out_size)
{
    const float* x       = (const float*)d_in[0];
    const float* noise   = (const float*)d_in[1];
    const float* W_in    = (const float*)d_in[2];
    const float* W_rec   = (const float*)d_in[3];
    const float* W_out_w = (const float*)d_in[4];
    const float* W_out_b = (const float*)d_in[5];
    const float* bias    = (const float*)d_in[6];
    float* out = (float*)d_out;

    static bool attr_done = false;
    if (!attr_done) {
        (void)cudaFuncSetAttribute(rnn_persistent_kernel,
                                   cudaFuncAttributeMaxDynamicSharedMemorySize,
                                   SMEM_BYTES);
        attr_done = true;
    }

    rnn_persistent_kernel<<<128, 256, SMEM_BYTES>>>(
        x, noise, W_in, W_rec, W_out_w, W_out_b, bias, out);
}

// round 6
// speedup vs baseline: 1.1603x; 1.0994x over previous
#include <cuda_runtime.h>
#include <cstdint>
#include <cstddef>

#define N_REC   256
#define T_STEPS 1000
#define NI      3
#define NO      3
#define ALPHA_F 0.2f
#define LEAK_F  0.8f
#define NOISE_SCALE_F 0.03162277660168379f

#define THREADS 512
#define WROW    68          // smem W row stride in floats (17 x 16B, conflict-free)
// floats: rbuf 1024 | wsh 512*68=34816 | wout 768 | wb 4 | part 512
#define SMEM_FLOATS (1024 + 512 * WROW + 768 + 4 + 512)
#define SMEM_BYTES  (SMEM_FLOATS * 4)

__device__ __forceinline__ unsigned long long pk2(float x, float y) {
    unsigned long long r;
    asm("mov.b64 %0, {%1, %2};" : "=l"(r) : "f"(x), "f"(y));
    return r;
}
__device__ __forceinline__ void upk2(unsigned long long v, float& x, float& y) {
    asm("mov.b64 {%0, %1}, %2;" : "=f"(x), "=f"(y) : "l"(v));
}
// Blackwell packed dual-fp32 FMA (sm_100+).
__device__ __forceinline__ unsigned long long ffma2(unsigned long long a,
                                                    unsigned long long b,
                                                    unsigned long long c) {
    unsigned long long d;
    asm("fma.rn.f32x2 %0, %1, %2, %3;" : "=l"(d) : "l"(a), "l"(b), "l"(c));
    return d;
}

// Output projection for one batch's step, one warp, overlapped with the
// h=0 update phase. rb = rbuf slice (256 floats).
__device__ __forceinline__ void emit_out(const float* __restrict__ rb,
                                         const float* __restrict__ wout_s,
                                         const float* __restrict__ wb3,
                                         float* __restrict__ out,
                                         int bidx, int tstore, int lane)
{
    const float4* rv = reinterpret_cast<const float4*>(rb);
    float4 ra = rv[lane];
    float4 rc = rv[32 + lane];
    const float4* w0 = reinterpret_cast<const float4*>(wout_s);
    const float4* w1 = reinterpret_cast<const float4*>(wout_s + 256);
    const float4* w2 = reinterpret_cast<const float4*>(wout_s + 512);
    float4 a0 = w0[lane], c0 = w0[32 + lane];
    float4 a1 = w1[lane], c1 = w1[32 + lane];
    float4 a2 = w2[lane], c2 = w2[32 + lane];

    float p0 = ra.x*a0.x + ra.y*a0.y + ra.z*a0.z + ra.w*a0.w
             + rc.x*c0.x + rc.y*c0.y + rc.z*c0.z + rc.w*c0.w;
    float p1 = ra.x*a1.x + ra.y*a1.y + ra.z*a1.z + ra.w*a1.w
             + rc.x*c1.x + rc.y*c1.y + rc.z*c1.z + rc.w*c1.w;
    float p2 = ra.x*a2.x + ra.y*a2.y + ra.z*a2.z + ra.w*a2.w
             + rc.x*c2.x + rc.y*c2.y + rc.z*c2.z + rc.w*c2.w;

    #pragma unroll
    for (int off = 16; off > 0; off >>= 1) {
        p0 += __shfl_xor_sync(0xffffffffu, p0, off);
        p1 += __shfl_xor_sync(0xffffffffu, p1, off);
        p2 += __shfl_xor_sync(0xffffffffu, p2, off);
    }
    if (lane == 0) {
        float* o = out + ((size_t)bidx * T_STEPS + tstore) * NO;
        o[0] = p0 + wb3[0];
        o[1] = p1 + wb3[1];
        o[2] = p2 + wb3[2];
    }
}

__global__ __launch_bounds__(THREADS, 1)
void rnn_persistent_kernel(const float* __restrict__ x,
                           const float* __restrict__ noise,
                           const float* __restrict__ W_in,
                           const float* __restrict__ W_rec,
                           const float* __restrict__ W_out_w,
                           const float* __restrict__ W_out_b,
                           const float* __restrict__ bias,
                           float* __restrict__ out)
{
    extern __shared__ float smem[];
    float*  rbuf   = smem;                     // [2 buf][2 batch][256]
    float*  wsh    = smem + 1024;              // [512 logical rows][WROW]
    float*  wout_s = wsh + 512 * WROW;         // [3][256]
    float*  wb3    = wout_s + 768;             // [3] (+1 pad)
    float2* part   = reinterpret_cast<float2*>(wb3 + 4);  // [256]

    const int tid  = threadIdx.x;
    const int lane = tid & 31;
    const int warp = tid >> 5;
    const int n    = tid & 255;                // row / neuron
    const int h    = tid >> 8;                 // k-half: 0 -> [0,128), 1 -> [128,256)
    const int b0   = blockIdx.x * 2;

    // ---- W row n, k in [h*128, h*128+64): 64 floats -> 32 packed regs ----
    unsigned long long w[32];
    {
        const float4* wr4 =
            reinterpret_cast<const float4*>(W_rec + (size_t)n * N_REC + h * 128);
        #pragma unroll
        for (int i = 0; i < 16; i++) {
            float4 v = wr4[i];
            w[2 * i]     = pk2(v.x, v.y);
            w[2 * i + 1] = pk2(v.z, v.w);
        }
        // k in [h*128+64, h*128+128): 64 floats -> SMEM padded row
        float4* wrow = reinterpret_cast<float4*>(wsh + (size_t)(h * 256 + n) * WROW);
        #pragma unroll
        for (int i = 0; i < 16; i++) wrow[i] = wr4[16 + i];
    }
    // ---- W_out / bias -> SMEM ----
    for (int idx = tid; idx < NO * N_REC; idx += THREADS) wout_s[idx] = W_out_w[idx];
    if (tid < NO) wb3[tid] = W_out_b[tid];

    // per-row constants, needed only by h=0 (update owners)
    const float wi0 = W_in[n * 3 + 0], wi1 = W_in[n * 3 + 1], wi2 = W_in[n * 3 + 2];
    const float bi  = bias[n];

    // initial state r = 0 in buffer 0 (512 floats, one per thread)
    rbuf[tid] = 0.f;

    const float* nzp0 = noise + (size_t)b0 * T_STEPS * N_REC + n;
    const float* nzp1 = nzp0 + (size_t)T_STEPS * N_REC;
    const float* xp0  = x + (size_t)b0 * T_STEPS * NI;
    const float* xp1  = xp0 + (size_t)T_STEPS * NI;

    float rold0 = 0.f, rold1 = 0.f;

    __syncthreads();

    const float4* wsv =
        reinterpret_cast<const float4*>(wsh + (size_t)(h * 256 + n) * WROW);

    for (int t = 0; t < T_STEPS; t++) {
        const int cur = t & 1, nxt = cur ^ 1;

        float nz0 = 0.f, nz1 = 0.f, x00 = 0.f, x01 = 0.f, x02 = 0.f,
              x10 = 0.f, x11 = 0.f, x12 = 0.f;
        if (h == 0) {   // prefetch drive inputs (used after the dot phase)
            nz0 = __ldg(nzp0 + t * N_REC);
            nz1 = __ldg(nzp1 + t * N_REC);
            x00 = __ldg(xp0 + t * 3 + 0);
            x01 = __ldg(xp0 + t * 3 + 1);
            x02 = __ldg(xp0 + t * 3 + 2);
            x10 = __ldg(xp1 + t * 3 + 0);
            x11 = __ldg(xp1 + t * 3 + 1);
            x12 = __ldg(xp1 + t * 3 + 2);
        }

        // ---- half-row dot: k in [h*128, h*128+128), both batches ----
        const float4* rb0 = reinterpret_cast<const float4*>(rbuf + cur * 512 + h * 128);
        const float4* rb1 = rb0 + 64;  // +256 floats = batch 1

        unsigned long long s0 = 0, t0a = 0, s1 = 0, t1a = 0;
        #pragma unroll
        for (int i = 0; i < 16; i++) {          // W from registers
            float4 q0 = rb0[i];
            float4 q1 = rb1[i];
            s0  = ffma2(w[2 * i],     pk2(q0.x, q0.y), s0);
            t0a = ffma2(w[2 * i + 1], pk2(q0.z, q0.w), t0a);
            s1  = ffma2(w[2 * i],     pk2(q1.x, q1.y), s1);
            t1a = ffma2(w[2 * i + 1], pk2(q1.z, q1.w), t1a);
        }
        #pragma unroll
        for (int i = 0; i < 16; i++) {          // W from SMEM
            float4 wv = wsv[i];
            unsigned long long wp0 = pk2(wv.x, wv.y);
            unsigned long long wp1 = pk2(wv.z, wv.w);
            float4 q0 = rb0[16 + i];
            float4 q1 = rb1[16 + i];
            s0  = ffma2(wp0, pk2(q0.x, q0.y), s0);
            t0a = ffma2(wp1, pk2(q0.z, q0.w), t0a);
            s1  = ffma2(wp0, pk2(q1.x, q1.y), s1);
            t1a = ffma2(wp1, pk2(q1.z, q1.w), t1a);
        }
        float e0, e1, e2, e3;
        upk2(s0, e0, e1); upk2(t0a, e2, e3);
        const float d0 = (e0 + e1) + (e2 + e3);
        upk2(s1, e0, e1); upk2(t1a, e2, e3);
        const float d1 = (e0 + e1) + (e2 + e3);

        if (h == 1) part[n] = make_float2(d0, d1);
        __syncthreads();

        if (h == 0) {
            const float2 pp = part[n];
            const float dot0 = d0 + pp.x;
            const float dot1 = d1 + pp.y;
            const float u0 = fmaf(NOISE_SCALE_F, nz0, bi) + x00*wi0 + x01*wi1 + x02*wi2;
            const float u1 = fmaf(NOISE_SCALE_F, nz1, bi) + x10*wi0 + x11*wi1 + x12*wi2;
            const float rn0 = LEAK_F * rold0 + ALPHA_F * fmaxf(dot0 + u0, 0.f);
            const float rn1 = LEAK_F * rold1 + ALPHA_F * fmaxf(dot1 + u1, 0.f);
            rold0 = rn0; rold1 = rn1;
            rbuf[nxt * 512 + n]       = rn0;
            rbuf[nxt * 512 + 256 + n] = rn1;
        } else if (t > 0 && (warp == 8 || warp == 9)) {
            // h=1 warps are idle during the update window: emit output t-1
            emit_out(rbuf + cur * 512 + (warp - 8) * 256, wout_s, wb3, out,
                     b0 + (warp - 8), t - 1, lane);
        }
        __syncthreads();
    }

    // final output t = T-1: final r is in buffer (T_STEPS & 1) = 0
    if (warp == 8 || warp == 9) {
        emit_out(rbuf + (T_STEPS & 1) * 512 + (warp - 8) * 256, wout_s, wb3, out,
                 b0 + (warp - 8), T_STEPS - 1, lane);
    }
}

extern "C" void kernel_launch(void* const* d_in, const int* in_sizes, int n_in,
                              void* d_out, int out_size)
{
    const float* x       = (const float*)d_in[0];
    const float* noise   = (const float*)d_in[1];
    const float* W_in    = (const float*)d_in[2];
    const float* W_rec   = (const float*)d_in[3];
    const float* W_out_w = (const float*)d_in[4];
    const float* W_out_b = (const float*)d_in[5];
    const float* bias    = (const float*)d_in[6];
    float* out = (float*)d_out;

    static bool attr_done = false;
    if (!attr_done) {
        (void)cudaFuncSetAttribute(rnn_persistent_kernel,
                                   cudaFuncAttributeMaxDynamicSharedMemorySize,
                                   SMEM_BYTES);
        attr_done = true;
    }

    rnn_persistent_kernel<<<128, THREADS, SMEM_BYTES>>>(
        x, noise, W_in, W_rec, W_out_w, W_out_b, bias, out);
}